// round 16
// baseline (speedup 1.0000x reference)
#include <cuda_runtime.h>
#include <cstdint>

// ---------------------------------------------------------------------------
// HungarianPredictor: B=2048, N=24, D=256
//   cost[b,i,j] = 1 - <normalize(prev[b,i]), normalize(slots[b,j])>
//   col = hungarian(cost)  (Jonker-Volgenant / e-maxx formulation)
//   out[b,i,:] = slots[b, col[b,i], :]
// ---------------------------------------------------------------------------

#define NSLOT   24
#define DDIM    256
#define ROWPAD  260                    // 1040 B row stride: 16B aligned, 8-lane-phase conflict-free
#define NN      (NSLOT * NSLOT)        // 576
#define MAXB    2048
#define HINF    1e9f

static const int SMEM_BYTES = 48 * ROWPAD * 4;   // 49,920 B (prev rows 0..23, cur rows 24..47)

__device__ float g_cost[MAXB * NN];
__device__ int   g_col [MAXB * NSLOT];

__device__ __forceinline__ unsigned long long fma2(unsigned long long a,
                                                   unsigned long long b,
                                                   unsigned long long c) {
    unsigned long long d;
    asm("fma.rn.f32x2 %0, %1, %2, %3;" : "=l"(d) : "l"(a), "l"(b), "l"(c));
    return d;
}

__device__ __forceinline__ float hsum2(unsigned long long v) {
    float lo = __uint_as_float((unsigned)(v & 0xffffffffu));
    float hi = __uint_as_float((unsigned)(v >> 32));
    return lo + hi;
}

// order-preserving float->uint key (monotone: a<b  <=>  key(a)<key(b))
__device__ __forceinline__ unsigned fkey(float f) {
    unsigned b = __float_as_uint(f);
    return (b & 0x80000000u) ? ~b : (b | 0x80000000u);
}
__device__ __forceinline__ float funkey(unsigned k) {
    return __uint_as_float((k & 0x80000000u) ? (k & 0x7fffffffu) : ~k);
}

// ---------------------------------------------------------------------------
// Kernel 1: per-batch cost matrix (R10 form — best measured).
// One block per batch, 256 threads: fused load+norm (8 warps x 6 rows), then
// dot on warps 0-3 (6 prev rows broadcast, lane j -> cur col j).
// ---------------------------------------------------------------------------
__global__ __launch_bounds__(256)
void cost_kernel(const float* __restrict__ slots, const float* __restrict__ prev) {
    extern __shared__ float s[];
    __shared__ float s_inv[48];
    const int b    = blockIdx.x;
    const int tid  = threadIdx.x;
    const int w    = tid >> 5;
    const int lane = tid & 31;

    const int srow = (w < 4) ? 6 * w : NSLOT + 6 * (w - 4);
    const float* base = (w < 4) ? (prev  + (size_t)b * (NSLOT * DDIM) + (6 * w) * DDIM)
                                : (slots + (size_t)b * (NSLOT * DDIM) + (6 * (w - 4)) * DDIM);
    float4 v0[6], v1[6];
    #pragma unroll
    for (int rr = 0; rr < 6; ++rr) {               // 12 LDG.128 in flight
        const float4* rp = (const float4*)(base + rr * DDIM);
        v0[rr] = rp[lane];
        v1[rr] = rp[lane + 32];
    }
    #pragma unroll
    for (int rr = 0; rr < 6; ++rr) {
        *(float4*)&s[(srow + rr) * ROWPAD + lane * 4]        = v0[rr];
        *(float4*)&s[(srow + rr) * ROWPAD + (lane + 32) * 4] = v1[rr];
        float ss = v0[rr].x * v0[rr].x;
        ss = fmaf(v0[rr].y, v0[rr].y, ss);
        ss = fmaf(v0[rr].z, v0[rr].z, ss);
        ss = fmaf(v0[rr].w, v0[rr].w, ss);
        ss = fmaf(v1[rr].x, v1[rr].x, ss);
        ss = fmaf(v1[rr].y, v1[rr].y, ss);
        ss = fmaf(v1[rr].z, v1[rr].z, ss);
        ss = fmaf(v1[rr].w, v1[rr].w, ss);
        #pragma unroll
        for (int o = 16; o; o >>= 1) ss += __shfl_xor_sync(0xffffffffu, ss, o);
        if (lane == 0) s_inv[srow + rr] = 1.f / fmaxf(sqrtf(ss), 1e-12f);
    }
    __syncthreads();

    if (w >= 4) return;

    if (lane < NSLOT) {
        const int r0 = w * 6;
        const float* cj = &s[(NSLOT + lane) * ROWPAD];
        unsigned long long acc[6];
        #pragma unroll
        for (int rr = 0; rr < 6; ++rr) acc[rr] = 0ull;

        #pragma unroll 4
        for (int k4 = 0; k4 < 64; ++k4) {
            ulonglong2 c = *(const ulonglong2*)&cj[k4 * 4];      // conflict-free per 8-lane phase
            #pragma unroll
            for (int rr = 0; rr < 6; ++rr) {
                ulonglong2 a = *(const ulonglong2*)&s[(r0 + rr) * ROWPAD + k4 * 4];  // broadcast (free)
                acc[rr] = fma2(a.x, c.x, acc[rr]);
                acc[rr] = fma2(a.y, c.y, acc[rr]);
            }
        }

        const float invj = s_inv[NSLOT + lane];
        float* cg = g_cost + (size_t)b * NN;
        #pragma unroll
        for (int rr = 0; rr < 6; ++rr)
            cg[(r0 + rr) * NSLOT + lane] = 1.f - hsum2(acc[rr]) * s_inv[r0 + rr] * invj;
    }
}

// ---------------------------------------------------------------------------
// Kernel 2: Hungarian, TWO batches per warp, chains interleaved for ILP.
// Each chain is ~85% latency stall; the second solver rides in the first
// one's stall shadow -> ~2x throughput on the serial phase at the same warp
// count.  All collectives execute unconditionally; warp-uniform `act` flags
// freeze a finished solver's state.  Argmin = order-preserving key +
// redux.min + ballot/ffs (first-index tie-break = jnp.argmin).  Augment:
// mark-on-path walks interleaved, then one parallel relink each.
// ---------------------------------------------------------------------------
__global__ __launch_bounds__(128)
void hungarian_kernel(int B) {
    __shared__ float sc[8][NN];
    const int w    = threadIdx.x >> 5;
    const int lane = threadIdx.x & 31;
    const int ba   = blockIdx.x * 8 + w * 2;      // this warp's two batches
    const int bb   = ba + 1;
    if (ba >= B) return;
    const bool hasb = (bb < B);
    const unsigned FULL = 0xffffffffu;

    // load both cost matrices (contiguous in g_cost -> float4 stream)
    {
        const float4* src = (const float4*)(g_cost + (size_t)ba * NN);
        float4* dst = (float4*)sc[w * 2];
        const int n4 = hasb ? 2 * NN / 4 : NN / 4;
        for (int t = lane; t < n4; t += 32) dst[t] = src[t];
    }
    __syncwarp();

    const float* ca = sc[w * 2];
    const float* cb = hasb ? sc[w * 2 + 1] : sc[w * 2];

    float va = 0.f, vb = 0.f;      // column potentials
    float upa = 0.f, upb = 0.f;    // u[p[lane]]
    int   pa = -1,  pb = -1;       // row assigned to this column

    for (int i = 0; i < NSLOT; ++i) {
        if (lane == NSLOT) { pa = i; upa = 0.f; pb = i; upb = 0.f; }
        float minva = HINF, minvb = HINF;
        int   waya = 0, wayb = 0;
        bool  useda = false, usedb = false;
        int   j0a = NSLOT, j0b = NSLOT;
        int   i0a = i,     i0b = i;        // p[virtual] just set to i
        float u0a = 0.f,   u0b = 0.f;
        bool  acta = true, actb = hasb;

        for (int it = 0; it < NSLOT + 2 && (acta || actb); ++it) {
            if (acta && lane == j0a) useda = true;
            if (actb && lane == j0b) usedb = true;
            float cura = (acta && lane < NSLOT && !useda) ? (ca[i0a * NSLOT + lane] - u0a - va) : HINF;
            float curb = (actb && lane < NSLOT && !usedb) ? (cb[i0b * NSLOT + lane] - u0b - vb) : HINF;
            if (acta && cura < minva) { minva = cura; waya = j0a; }
            if (actb && curb < minvb) { minvb = curb; wayb = j0b; }
            float maska = (lane < NSLOT && !useda) ? minva : HINF;
            float maskb = (lane < NSLOT && !usedb) ? minvb : HINF;

            unsigned ka = fkey(maska);
            unsigned kb = fkey(maskb);
            unsigned ma = __reduce_min_sync(FULL, ka);
            unsigned mb = __reduce_min_sync(FULL, kb);
            unsigned bla = __ballot_sync(FULL, ka == ma);
            unsigned blb = __ballot_sync(FULL, kb == mb);
            float da = funkey(ma);
            float db = funkey(mb);
            int j1a = __ffs(bla) - 1;
            int j1b = __ffs(blb) - 1;

            if (acta) {
                if (useda)              { upa += da; va -= da; }
                else if (lane < NSLOT)  { minva -= da; }
                j0a = j1a;
            }
            if (actb) {
                if (usedb)              { upb += db; vb -= db; }
                else if (lane < NSLOT)  { minvb -= db; }
                j0b = j1b;
            }

            i0a = __shfl_sync(FULL, pa,  j0a);
            u0a = __shfl_sync(FULL, upa, j0a);
            i0b = __shfl_sync(FULL, pb,  j0b);
            u0b = __shfl_sync(FULL, upb, j0b);
            if (acta && i0a < 0) acta = false;    // reached a free column
            if (actb && i0b < 0) actb = false;
        }

        // augment both paths: mark on-path lanes (1 shfl/step, interleaved),
        // then one parallel relink per problem (old p/up values semantics).
        bool onpa = false, onpb = false;
        int  ja = j0a, jb = hasb ? j0b : NSLOT;
        while (ja != NSLOT || jb != NSLOT) {
            if (ja != NSLOT) { if (lane == ja) onpa = true; ja = __shfl_sync(FULL, waya, ja); }
            if (jb != NSLOT) { if (lane == jb) onpb = true; jb = __shfl_sync(FULL, wayb, jb); }
        }
        int   npa  = __shfl_sync(FULL, pa,  waya);
        float nupa = __shfl_sync(FULL, upa, waya);
        int   npb  = __shfl_sync(FULL, pb,  wayb);
        float nupb = __shfl_sync(FULL, upb, wayb);
        if (onpa) { pa = npa; upa = nupa; }
        if (onpb) { pb = npb; upb = nupb; }
    }

    // p = row matched to column `lane`  ->  col_ind[p] = lane
    if (lane < NSLOT) {
        g_col[ba * NSLOT + pa] = lane;
        if (hasb) g_col[bb * NSLOT + pb] = lane;
    }
}

// ---------------------------------------------------------------------------
// Kernel 3: gather.  out[b,r,:] = slots[b, col[b,r], :]  (float4 streaming)
// grid = B*6 blocks x 256 threads: exactly one float4 per thread.
// ---------------------------------------------------------------------------
__global__ __launch_bounds__(256)
void gather_kernel(const float* __restrict__ slots, float* __restrict__ out) {
    const int bx = blockIdx.x;
    const int b  = bx / 6;
    const int within = (bx % 6) * 256 + threadIdx.x;   // 0..1535 (float4 idx in batch)
    const int r  = within >> 6;
    const int d4 = within & 63;
    const int src = g_col[b * NSLOT + r];
    const float4* sp = (const float4*)(slots + (size_t)b * (NSLOT * DDIM));
    float4 val = sp[src * 64 + d4];
    ((float4*)(out + (size_t)b * (NSLOT * DDIM)))[r * 64 + d4] = val;
}

// ---------------------------------------------------------------------------
extern "C" void kernel_launch(void* const* d_in, const int* in_sizes, int n_in,
                              void* d_out, int out_size) {
    const float* slots = (const float*)d_in[0];
    const float* prev  = (const float*)d_in[1];
    float* out = (float*)d_out;
    const int B = in_sizes[0] / (NSLOT * DDIM);   // 2048

    cudaFuncSetAttribute(cost_kernel, cudaFuncAttributeMaxDynamicSharedMemorySize, SMEM_BYTES);

    cost_kernel<<<B, 256, SMEM_BYTES>>>(slots, prev);
    hungarian_kernel<<<(B + 7) / 8, 128>>>(B);    // 4 warps/block x 2 batches/warp
    gather_kernel<<<B * 6, 256>>>(slots, out);
}